// round 1
// baseline (speedup 1.0000x reference)
#include <cuda_runtime.h>
#include <math.h>

#define NB   32
#define NP   8732
#define NC   21
#define TOPK 200
#define PA   8736          // NP padded
#define FULLM 0xFFFFFFFFu

// Scratch: transposed confidences conf_T[b][c][p]  (23.5 MB, static device array — allowed)
__device__ float g_confT[(size_t)NB * NC * NP];

// ---------------------------------------------------------------------------
// Kernel 1: tiled transpose  conf[b][p][c] -> g_confT[b][c][p]
// ---------------------------------------------------------------------------
#define TP 512
__global__ void transpose_kernel(const float* __restrict__ conf) {
    __shared__ float s[TP * NC];          // 43008 B static
    const int nt  = (NP + TP - 1) / TP;   // 18
    const int b   = blockIdx.x / nt;
    const int t   = blockIdx.x % nt;
    const int p0  = t * TP;
    const int np  = min(TP, NP - p0);
    const float* src = conf + ((size_t)b * NP + p0) * NC;
    const int n  = np * NC;
    const int nv = n >> 2;
    const float4* src4 = (const float4*)src;
    for (int i = threadIdx.x; i < nv; i += blockDim.x) {
        float4 v = src4[i];
        s[i * 4 + 0] = v.x; s[i * 4 + 1] = v.y;
        s[i * 4 + 2] = v.z; s[i * 4 + 3] = v.w;
    }
    for (int i = nv * 4 + threadIdx.x; i < n; i += blockDim.x) s[i] = src[i];
    __syncthreads();
    for (int c = 0; c < NC; c++) {
        float* dst = g_confT + ((size_t)b * NC + c) * NP + p0;
        for (int p = threadIdx.x; p < np; p += blockDim.x)
            dst[p] = s[p * NC + c];       // stride-21 smem read: 21 coprime 32 -> no conflicts
    }
}

// ---------------------------------------------------------------------------
// Kernel 2: per-(b,c) top-200 radix select + decode + NMS + compacted output
// ---------------------------------------------------------------------------
__device__ __forceinline__ unsigned mapf(float f) {
    unsigned u = __float_as_uint(f);
    return (u & 0x80000000u) ? ~u : (u | 0x80000000u);
}
__device__ __forceinline__ float unmapf(unsigned m) {
    unsigned u = (m & 0x80000000u) ? (m ^ 0x80000000u) : ~m;
    return __uint_as_float(u);
}

// warp-aggregated histogram increment (all 32 lanes must be converged)
__device__ __forceinline__ void aggHist(unsigned* hist, int d, bool in) {
    unsigned mm = __match_any_sync(FULLM, d);
    int lane = threadIdx.x & 31;
    int leader = __ffs(mm) - 1;
    if (in && lane == leader) atomicAdd(&hist[d], (unsigned)__popc(mm));
}

// smem layout (bytes):
//   vals  : PA u32                      (mapped thresholded scores)
//   candA : PA u32
//   candB : PA u32
//   hist  : 256 u32
//   ctr   : 8 u32   [0]=def append ctr, [1]=new cand ctr, [2]=t
//   defs  : 512 u64
#define SMEM_BYTES ((PA * 3 + 256 + 8) * 4 + 512 * 8)

__global__ __launch_bounds__(256, 2)
void select_kernel(const float* __restrict__ loc,
                   const float* __restrict__ prior,
                   float* __restrict__ out) {
    const int blk = blockIdx.x;
    const int b   = blk / NC;
    const int c   = blk % NC;
    const int tid = threadIdx.x;
    float* outBase = out + (size_t)blk * (TOPK * 5);

    // class 0 is zeroed by the reference
    if (c == 0) {
        for (int i = tid; i < TOPK * 5; i += 256) outBase[i] = 0.0f;
        return;
    }
    // zero my output slab up front (non-kept rows must be 0; d_out is poisoned)
    for (int i = tid; i < TOPK * 5; i += 256) outBase[i] = 0.0f;

    extern __shared__ unsigned char smraw[];
    unsigned* vals  = (unsigned*)smraw;
    unsigned* candA = vals  + PA;
    unsigned* candB = candA + PA;
    unsigned* hist  = candB + PA;
    unsigned* ctr   = hist + 256;
    unsigned long long* defs = (unsigned long long*)(ctr + 8);

    // ---- pass 1: load column (coalesced, L2-hot), map, store, round-0 histogram
    if (tid < 256) hist[tid] = 0;
    if (tid == 0) { ctr[0] = 0; ctr[1] = 0; }
    __syncthreads();

    const float* col = g_confT + (size_t)blk * NP;
    for (int base = 0; base < NP; base += 256) {
        int i = base + tid;
        bool in = i < NP;
        int d = 300;
        if (in) {
            float f = col[i];
            float s = (f > 0.01f) ? f : -1.0f;
            unsigned m = mapf(s);
            vals[i] = m;
            d = (int)(m >> 24);
        }
        aggHist(hist, d, in);
    }
    __syncthreads();

    // ---- radix select: keep top-200 definite + boundary candidates (<=512 total)
    int defCnt = 0;
    int nc = NP;
    bool srcAll = true;
    unsigned* src = candA;
    unsigned* dst = candA;
    int shift = 56;
    int total = 0;

    while (true) {
        if (tid == 0) {
            int acc = 0, t = 0;
            for (int d = 255; d >= 0; d--) {
                int h = (int)hist[d];
                if (defCnt + acc + h > TOPK) { t = d; break; }
                acc += h;
            }
            ctr[2] = (unsigned)t;
            ctr[0] = (unsigned)defCnt;
            ctr[1] = 0;
        }
        __syncthreads();
        int t = (int)ctr[2];

        for (int base = 0; base < nc; base += 256) {
            int i = base + tid;
            bool in = i < nc;
            unsigned idx = 0; unsigned long long key = 0; int d = -1;
            if (in) {
                idx = srcAll ? (unsigned)i : src[i];
                key = ((unsigned long long)vals[idx] << 32) | (unsigned)(~idx);
                d = (int)((key >> shift) & 0xFF);
            }
            bool p1 = in && (d > t);
            bool p2 = in && (d == t);
            unsigned b1 = __ballot_sync(FULLM, p1);
            unsigned b2 = __ballot_sync(FULLM, p2);
            int lane = tid & 31;
            int base1 = 0, base2 = 0;
            if (lane == 0) {
                base1 = b1 ? (int)atomicAdd(&ctr[0], (unsigned)__popc(b1)) : 0;
                base2 = b2 ? (int)atomicAdd(&ctr[1], (unsigned)__popc(b2)) : 0;
            }
            base1 = __shfl_sync(FULLM, base1, 0);
            base2 = __shfl_sync(FULLM, base2, 0);
            unsigned lt = (1u << lane) - 1u;
            if (p1) defs[base1 + __popc(b1 & lt)] = key;
            if (p2) dst[base2 + __popc(b2 & lt)] = idx;
        }
        __syncthreads();
        defCnt = (int)ctr[0];
        nc = (int)ctr[1];

        if (defCnt + nc <= 512 || shift == 0) {
            // append remaining candidates (order irrelevant; sorted next)
            for (int i = tid; i < nc; i += 256) {
                unsigned idx = dst[i];
                defs[defCnt + i] =
                    ((unsigned long long)vals[idx] << 32) | (unsigned)(~idx);
            }
            total = defCnt + nc;
            if (total > 512) total = 512;   // unreachable safety
            __syncthreads();
            break;
        }

        // next round
        srcAll = false;
        src = dst;
        dst = (src == candA) ? candB : candA;
        shift -= 8;
        if (tid < 256) hist[tid] = 0;
        __syncthreads();
        for (int base = 0; base < nc; base += 256) {
            int i = base + tid;
            bool in = i < nc;
            int d = 300;
            if (in) {
                unsigned idx = src[i];
                unsigned long long key =
                    ((unsigned long long)vals[idx] << 32) | (unsigned)(~idx);
                d = (int)((key >> shift) & 0xFF);
            }
            aggHist(hist, d, in);
        }
        __syncthreads();
    }

    // ---- pad + bitonic sort 512 u64 ascending (top-200 read from the tail)
    for (int i = total + tid; i < 512; i += 256) defs[i] = 0ull;
    __syncthreads();
    for (int k = 2; k <= 512; k <<= 1) {
        for (int j = k >> 1; j > 0; j >>= 1) {
            for (int i = tid; i < 512; i += 256) {
                int ixj = i ^ j;
                if (ixj > i) {
                    unsigned long long a = defs[i], bb = defs[ixj];
                    bool up = ((i & k) == 0);
                    if ((a > bb) == up) { defs[i] = bb; defs[ixj] = a; }
                }
            }
            __syncthreads();
        }
    }

    // ---- decode boxes for top-200 (overlay NMS arrays on candA)
    float* bx1 = (float*)candA;
    float* by1 = bx1 + 256;
    float* bx2 = by1 + 256;
    float* by2 = bx2 + 256;
    float* sAr = by2 + 256;
    float* area = sAr + 256;
    int* supp = (int*)(area + 256);
    int* kept = supp + 256;
    int* posA = kept + 256;

    if (tid < TOPK) {
        unsigned long long key = defs[511 - tid];       // rank tid (descending)
        unsigned m   = (unsigned)(key >> 32);
        unsigned idx = ~((unsigned)key);
        float sv = unmapf(m);
        float4 l  = __ldg((const float4*)loc + ((size_t)b * NP + idx));
        float4 pr = __ldg((const float4*)prior + idx);
        float cx = pr.x + l.x * 0.1f * pr.z;
        float cy = pr.y + l.y * 0.1f * pr.w;
        float w  = pr.z * expf(l.z * 0.2f);
        float h  = pr.w * expf(l.w * 0.2f);
        float x1 = cx - w * 0.5f;
        float y1 = cy - h * 0.5f;
        float x2 = x1 + w;
        float y2 = y1 + h;
        bx1[tid] = x1; by1[tid] = y1; bx2[tid] = x2; by2[tid] = y2;
        sAr[tid] = sv;
        area[tid] = (x2 - x1) * (y2 - y1);
        supp[tid] = 0; kept[tid] = 0;
    }
    __syncthreads();

    // ---- greedy NMS: 200 sequential steps, 200 parallel lanes, IoU on the fly
    for (int j = 0; j < TOPK; j++) {
        bool isk = (sAr[j] > 0.01f) && (supp[j] == 0);
        if (tid == j) kept[j] = isk ? 1 : 0;
        if (isk && tid < TOPK && tid > j && supp[tid] == 0) {
            float xx1 = fmaxf(bx1[j], bx1[tid]);
            float yy1 = fmaxf(by1[j], by1[tid]);
            float xx2 = fminf(bx2[j], bx2[tid]);
            float yy2 = fminf(by2[j], by2[tid]);
            float iw = fmaxf(xx2 - xx1, 0.0f);
            float ih = fmaxf(yy2 - yy1, 0.0f);
            float inter = iw * ih;
            float uni = area[j] + area[tid] - inter;
            float iou = inter / uni;
            if (iou > 0.45f) supp[tid] = 1;
        }
        __syncthreads();
    }

    // ---- compact & write kept rows
    if (tid == 0) {
        int pp = 0;
        for (int i = 0; i < TOPK; i++) { posA[i] = pp; pp += kept[i]; }
    }
    __syncthreads();
    if (tid < TOPK && kept[tid]) {
        float* row = outBase + posA[tid] * 5;
        row[0] = sAr[tid];
        row[1] = bx1[tid];
        row[2] = by1[tid];
        row[3] = bx2[tid];
        row[4] = by2[tid];
    }
}

// ---------------------------------------------------------------------------
extern "C" void kernel_launch(void* const* d_in, const int* in_sizes, int n_in,
                              void* d_out, int out_size) {
    const float* loc   = (const float*)d_in[0];
    const float* conf  = (const float*)d_in[1];
    const float* prior = (const float*)d_in[2];
    float* out = (float*)d_out;

    cudaFuncSetAttribute(select_kernel,
                         cudaFuncAttributeMaxDynamicSharedMemorySize, SMEM_BYTES);

    const int nt = (NP + TP - 1) / TP;          // 18
    transpose_kernel<<<NB * nt, 256>>>(conf);
    select_kernel<<<NB * NC, 256, SMEM_BYTES>>>(loc, prior, out);
}

// round 2
// speedup vs baseline: 1.4348x; 1.4348x over previous
#include <cuda_runtime.h>
#include <math.h>

#define NB   32
#define NP   8732
#define NC   21
#define TOPK 200
#define PA   8736
#define NT   512
#define FULLM 0xFFFFFFFFu

// Scratch: transposed confidences conf_T[b][c][p]
__device__ float g_confT[(size_t)NB * NC * NP];

// ---------------------------------------------------------------------------
// Kernel 1: tiled transpose  conf[b][p][c] -> g_confT[b][c][p]
// ---------------------------------------------------------------------------
#define TP 512
__global__ void transpose_kernel(const float* __restrict__ conf) {
    __shared__ float s[TP * NC];
    const int nt  = (NP + TP - 1) / TP;   // 18
    const int b   = blockIdx.x / nt;
    const int t   = blockIdx.x % nt;
    const int p0  = t * TP;
    const int np  = min(TP, NP - p0);
    const float* src = conf + ((size_t)b * NP + p0) * NC;
    const int n  = np * NC;
    const int nv = n >> 2;
    const float4* src4 = (const float4*)src;
    for (int i = threadIdx.x; i < nv; i += blockDim.x) {
        float4 v = src4[i];
        s[i * 4 + 0] = v.x; s[i * 4 + 1] = v.y;
        s[i * 4 + 2] = v.z; s[i * 4 + 3] = v.w;
    }
    for (int i = nv * 4 + threadIdx.x; i < n; i += blockDim.x) s[i] = src[i];
    __syncthreads();
    for (int c = 0; c < NC; c++) {
        float* dst = g_confT + ((size_t)b * NC + c) * NP + p0;
        for (int p = threadIdx.x; p < np; p += blockDim.x)
            dst[p] = s[p * NC + c];
    }
}

// ---------------------------------------------------------------------------
__device__ __forceinline__ unsigned mapf(float f) {
    unsigned u = __float_as_uint(f);
    return (u & 0x80000000u) ? ~u : (u | 0x80000000u);
}
__device__ __forceinline__ float unmapf(unsigned m) {
    unsigned u = (m & 0x80000000u) ? (m ^ 0x80000000u) : ~m;
    return __uint_as_float(u);
}

__device__ __forceinline__ void aggHist(unsigned* hist, int d, bool in) {
    unsigned mm = __match_any_sync(FULLM, d);
    int lane = threadIdx.x & 31;
    int leader = __ffs(mm) - 1;
    if (in && lane == leader) atomicAdd(&hist[d], (unsigned)__popc(mm));
}

// smem: vals PA u32 | candA PA u32 | candB PA u32 | hist 256 | ctr 16 | defs 512 u64
#define SMEM_BYTES ((PA * 3 + 256 + 16) * 4 + 512 * 8)

__global__ __launch_bounds__(NT, 2)
void select_kernel(const float* __restrict__ loc,
                   const float* __restrict__ prior,
                   float* __restrict__ out) {
    const int blk = blockIdx.x;
    const int b   = blk / NC;
    const int c   = blk % NC;
    const int tid = threadIdx.x;
    float* outBase = out + (size_t)blk * (TOPK * 5);

    // zero my output slab (poisoned by harness); class 0 stays zero
    for (int i = tid; i < TOPK * 5; i += NT) outBase[i] = 0.0f;
    if (c == 0) return;

    extern __shared__ unsigned char smraw[];
    unsigned* vals  = (unsigned*)smraw;
    unsigned* candA = vals  + PA;
    unsigned* candB = candA + PA;
    unsigned* hist  = candB + PA;
    unsigned* ctr   = hist + 256;          // [0]=def ctr [1]=cand ctr [2]=kmin [8..15]=warp totals
    unsigned long long* defs = (unsigned long long*)(ctr + 16);

    // ---- pass 1: load column, map+threshold, round-0 histogram
    if (tid < 256) hist[tid] = 0;
    __syncthreads();

    const float* col = g_confT + (size_t)blk * NP;
    for (int base = 0; base < NP; base += NT) {
        int i = base + tid;
        bool in = i < NP;
        int d = 300;
        if (in) {
            float f = col[i];
            float s = (f > 0.01f) ? f : -1.0f;
            unsigned m = mapf(s);
            vals[i] = m;
            d = (int)(m >> 24);
        }
        aggHist(hist, d, in);
    }
    __syncthreads();

    // ---- radix select loop
    int defCnt = 0;
    int nc = NP;
    bool srcAll = true;
    unsigned* src = candA;
    unsigned* dst = candA;
    int shift = 56;
    int total = 0;

    while (true) {
        // --- parallel threshold: t = max digit d with defCnt + suffixIncl(d) > TOPK
        if (tid == 0) ctr[2] = 256;
        __syncthreads();
        unsigned v = 0;
        if (tid < 256) {
            v = hist[255 - tid];
            #pragma unroll
            for (int off = 1; off < 32; off <<= 1) {
                unsigned n = __shfl_up_sync(FULLM, v, off);
                if ((tid & 31) >= off) v += n;
            }
            if ((tid & 31) == 31) ctr[8 + (tid >> 5)] = v;
        }
        __syncthreads();
        if (tid < 256) {
            unsigned add = 0;
            for (int w = 0; w < (tid >> 5); w++) add += ctr[8 + w];
            if ((unsigned)defCnt + v + add > (unsigned)TOPK)
                atomicMin(&ctr[2], (unsigned)tid);
        }
        if (tid == 0) { ctr[0] = (unsigned)defCnt; ctr[1] = 0; }
        __syncthreads();
        int t = 255 - (int)ctr[2];   // -1 if none overflow (everything definite)

        // --- partition: digit>t -> defs (keys), digit==t -> dst (indices)
        for (int base = 0; base < nc; base += NT) {
            int i = base + tid;
            bool in = i < nc;
            unsigned idx = 0; unsigned long long key = 0; int d = -1;
            if (in) {
                idx = srcAll ? (unsigned)i : src[i];
                key = ((unsigned long long)vals[idx] << 32) | (unsigned)(~idx);
                d = (int)((key >> shift) & 0xFF);
            }
            bool p1 = in && (d > t);
            bool p2 = in && (d == t);
            unsigned b1 = __ballot_sync(FULLM, p1);
            unsigned b2 = __ballot_sync(FULLM, p2);
            int lane = tid & 31;
            int base1 = 0, base2 = 0;
            if (lane == 0) {
                base1 = b1 ? (int)atomicAdd(&ctr[0], (unsigned)__popc(b1)) : 0;
                base2 = b2 ? (int)atomicAdd(&ctr[1], (unsigned)__popc(b2)) : 0;
            }
            base1 = __shfl_sync(FULLM, base1, 0);
            base2 = __shfl_sync(FULLM, base2, 0);
            unsigned lt = (1u << lane) - 1u;
            if (p1) defs[base1 + __popc(b1 & lt)] = key;
            if (p2) dst[base2 + __popc(b2 & lt)] = idx;
        }
        __syncthreads();
        defCnt = (int)ctr[0];
        nc = (int)ctr[1];

        if (defCnt + nc <= 512 || shift == 0) {
            for (int i = tid; i < nc; i += NT) {
                unsigned idx = dst[i];
                defs[defCnt + i] =
                    ((unsigned long long)vals[idx] << 32) | (unsigned)(~idx);
            }
            total = defCnt + nc;
            if (total > 512) total = 512;
            __syncthreads();
            break;
        }

        srcAll = false;
        src = dst;
        dst = (src == candA) ? candB : candA;
        shift -= 8;
        if (tid < 256) hist[tid] = 0;
        __syncthreads();
        for (int base = 0; base < nc; base += NT) {
            int i = base + tid;
            bool in = i < nc;
            int d = 300;
            if (in) {
                unsigned idx = src[i];
                unsigned long long key =
                    ((unsigned long long)vals[idx] << 32) | (unsigned)(~idx);
                d = (int)((key >> shift) & 0xFF);
            }
            aggHist(hist, d, in);
        }
        __syncthreads();
    }

    // ---- pad + bitonic sort 512 u64 ascending (top-200 = tail, descending)
    for (int i = total + tid; i < 512; i += NT) defs[i] = 0ull;
    __syncthreads();
    for (int k = 2; k <= 512; k <<= 1) {
        for (int j = k >> 1; j > 0; j >>= 1) {
            int i = tid;
            int ixj = i ^ j;
            if (i < 512 && ixj > i) {
                unsigned long long a = defs[i], bb = defs[ixj];
                bool up = ((i & k) == 0);
                if ((a > bb) == up) { defs[i] = bb; defs[ixj] = a; }
            }
            __syncthreads();
        }
    }

    // ---- decode top-200 into smem arrays (overlay on candA)
    float* bx1 = (float*)candA;
    float* by1 = bx1 + 256;
    float* bx2 = by1 + 256;
    float* by2 = bx2 + 256;
    float* sAr = by2 + 256;
    float* area = sAr + 256;
    unsigned* rows = (unsigned*)(area + 256);   // 200 x 8 u32 bit-matrix
    unsigned* keepw = rows + 200 * 8;           // 7 kept-mask words

    if (tid < TOPK) {
        unsigned long long key = defs[511 - tid];
        unsigned m   = (unsigned)(key >> 32);
        unsigned idx = ~((unsigned)key);
        float sv = unmapf(m);
        float4 l  = __ldg((const float4*)loc + ((size_t)b * NP + idx));
        float4 pr = __ldg((const float4*)prior + idx);
        float cx = pr.x + l.x * 0.1f * pr.z;
        float cy = pr.y + l.y * 0.1f * pr.w;
        float w  = pr.z * expf(l.z * 0.2f);
        float h  = pr.w * expf(l.w * 0.2f);
        float x1 = cx - w * 0.5f;
        float y1 = cy - h * 0.5f;
        float x2 = x1 + w;
        float y2 = y1 + h;
        bx1[tid] = x1; by1[tid] = y1; bx2[tid] = x2; by2[tid] = y2;
        sAr[tid] = sv;
        area[tid] = (x2 - x1) * (y2 - y1);
    }
    __syncthreads();

    // ---- build IoU>thresh bit matrix: rows[j] bit k set iff k>j && iou(j,k)>0.45
    for (int task = tid; task < TOPK * 7; task += NT) {
        int j = task / 7;
        int w = task % 7;
        unsigned bits = 0;
        int k0 = w * 32;
        if (k0 + 31 > j) {
            float x1j = bx1[j], y1j = by1[j], x2j = bx2[j], y2j = by2[j];
            float aj = area[j];
            #pragma unroll 4
            for (int kk = 0; kk < 32; kk++) {
                int k = k0 + kk;
                if (k > j && k < TOPK) {
                    float xx1 = fmaxf(x1j, bx1[k]);
                    float yy1 = fmaxf(y1j, by1[k]);
                    float xx2 = fminf(x2j, bx2[k]);
                    float yy2 = fminf(y2j, by2[k]);
                    float iw = fmaxf(xx2 - xx1, 0.0f);
                    float ih = fmaxf(yy2 - yy1, 0.0f);
                    float inter = iw * ih;
                    float uni = aj + area[k] - inter;
                    float iou = inter / uni;
                    if (iou > 0.45f) bits |= 1u << kk;
                }
            }
        }
        rows[j * 8 + w] = bits;
    }
    __syncthreads();

    // ---- sequential greedy propagation (single thread, pure bit ops)
    if (tid == 0) {
        unsigned supp[7], kw[7];
        #pragma unroll
        for (int i = 0; i < 7; i++) { supp[i] = 0; kw[i] = 0; }
        #pragma unroll
        for (int w = 0; w < 7; w++) {
            int nb = (w == 6) ? (TOPK - 6 * 32) : 32;
            for (int bs = 0; bs < nb; bs++) {
                int j = w * 32 + bs;
                bool isk = (sAr[j] > 0.01f) && !((supp[w] >> bs) & 1u);
                if (isk) {
                    kw[w] |= 1u << bs;
                    #pragma unroll
                    for (int ww = 0; ww < 7; ww++) supp[ww] |= rows[j * 8 + ww];
                }
            }
        }
        #pragma unroll
        for (int i = 0; i < 7; i++) keepw[i] = kw[i];
    }
    __syncthreads();

    // ---- parallel compaction via popcount, write kept rows
    if (tid < TOPK) {
        int w = tid >> 5, bs = tid & 31;
        unsigned kwv = keepw[w];
        if ((kwv >> bs) & 1u) {
            int pos = 0;
            for (int ww = 0; ww < w; ww++) pos += __popc(keepw[ww]);
            pos += __popc(kwv & ((1u << bs) - 1u));
            float* row = outBase + pos * 5;
            row[0] = sAr[tid];
            row[1] = bx1[tid];
            row[2] = by1[tid];
            row[3] = bx2[tid];
            row[4] = by2[tid];
        }
    }
}

// ---------------------------------------------------------------------------
extern "C" void kernel_launch(void* const* d_in, const int* in_sizes, int n_in,
                              void* d_out, int out_size) {
    const float* loc   = (const float*)d_in[0];
    const float* conf  = (const float*)d_in[1];
    const float* prior = (const float*)d_in[2];
    float* out = (float*)d_out;

    cudaFuncSetAttribute(select_kernel,
                         cudaFuncAttributeMaxDynamicSharedMemorySize, SMEM_BYTES);

    const int nt = (NP + TP - 1) / TP;          // 18
    transpose_kernel<<<NB * nt, 256>>>(conf);
    select_kernel<<<NB * NC, NT, SMEM_BYTES>>>(loc, prior, out);
}

// round 3
// speedup vs baseline: 2.1511x; 1.4992x over previous
#include <cuda_runtime.h>
#include <math.h>

#define NB   32
#define NP   8732
#define NC   21
#define TOPK 200
#define NT   512
#define NP4  (NP / 4)      // 2183
#define FULLM 0xFFFFFFFFu

// Transposed, thresholded, order-mapped confidences: key32[b][c][p]
__device__ unsigned g_confT[(size_t)NB * NC * NP];

// ---------------------------------------------------------------------------
// Kernel 1: tiled transpose + threshold + monotonic map
// ---------------------------------------------------------------------------
#define TP 512
__global__ void transpose_kernel(const float* __restrict__ conf) {
    __shared__ float s[TP * NC];
    const int nt  = (NP + TP - 1) / TP;   // 18
    const int b   = blockIdx.x / nt;
    const int t   = blockIdx.x % nt;
    const int p0  = t * TP;
    const int np  = min(TP, NP - p0);
    const float* src = conf + ((size_t)b * NP + p0) * NC;
    const int n  = np * NC;
    const int nv = n >> 2;
    const float4* src4 = (const float4*)src;
    for (int i = threadIdx.x; i < nv; i += blockDim.x) {
        float4 v = src4[i];
        s[i * 4 + 0] = v.x; s[i * 4 + 1] = v.y;
        s[i * 4 + 2] = v.z; s[i * 4 + 3] = v.w;
    }
    for (int i = nv * 4 + threadIdx.x; i < n; i += blockDim.x) s[i] = src[i];
    __syncthreads();
    for (int c = 0; c < NC; c++) {
        unsigned* dst = g_confT + ((size_t)b * NC + c) * NP + p0;
        for (int p = threadIdx.x; p < np; p += blockDim.x) {
            float f  = s[p * NC + c];
            float sv = (f > 0.01f) ? f : -1.0f;
            unsigned u = __float_as_uint(sv);
            dst[p] = (u & 0x80000000u) ? ~u : (u | 0x80000000u);
        }
    }
}

// ---------------------------------------------------------------------------
__device__ __forceinline__ float unmapf(unsigned m) {
    unsigned u = (m & 0x80000000u) ? (m ^ 0x80000000u) : ~m;
    return __uint_as_float(u);
}

// warp-aggregated histogram add (all 32 lanes converged)
__device__ __forceinline__ void aggHist(unsigned* hist, int d, bool in) {
    unsigned mm = __match_any_sync(FULLM, d);
    int lane = threadIdx.x & 31;
    if (in && lane == (__ffs(mm) - 1))
        atomicAdd(&hist[d], (unsigned)__popc(mm));
}

__global__ __launch_bounds__(NT, 3)
void select_kernel(const float* __restrict__ loc,
                   const float* __restrict__ prior,
                   float* __restrict__ out) {
    const int blk = blockIdx.x;
    const int b   = blk / NC;
    const int c   = blk % NC;
    const int tid = threadIdx.x;
    float* outBase = out + (size_t)blk * (TOPK * 5);

    for (int i = tid; i < TOPK * 5; i += NT) outBase[i] = 0.0f;
    if (c == 0) return;

    __shared__ unsigned hist[256];
    __shared__ unsigned ctr[16];
    __shared__ unsigned long long defs[256];
    __shared__ float4   boxs[TOPK];
    __shared__ float    areas[TOPK];
    __shared__ float    scores[TOPK];
    __shared__ unsigned rows[TOPK * 8];
    __shared__ unsigned keepw[8];
    __shared__ unsigned validw[8];
    __shared__ unsigned hasroww[8];

    const uint4* col4 = (const uint4*)(g_confT + (size_t)blk * NP);

    unsigned long long prefix = 0;
    unsigned long long C = 0;
    int shift = 56, defCnt = 0;

    const int FULL_IT = NP4 / NT;         // 4
    const int TAIL    = NP4 - FULL_IT * NT; // 135

    // ---------------- radix pivot search (histogram-only rounds) -----------
    while (true) {
        if (tid < 256) hist[tid] = 0;
        if (tid == 0) ctr[2] = 256;
        __syncthreads();

        for (int it = 0; it <= FULL_IT; it++) {
            int i = it * NT + tid;
            bool valid = (it < FULL_IT) || (tid < TAIL);
            uint4 m4 = valid ? col4[i] : make_uint4(0, 0, 0, 0);
            #pragma unroll
            for (int q = 0; q < 4; q++) {
                unsigned m = (q == 0) ? m4.x : (q == 1) ? m4.y : (q == 2) ? m4.z : m4.w;
                unsigned idx = (unsigned)(i * 4 + q);
                unsigned long long key = ((unsigned long long)m << 32) | (unsigned)(~idx);
                unsigned long long hi = (key ^ prefix) >> shift;
                bool in = valid && ((hi >> 8) == 0);
                aggHist(hist, in ? (int)(hi & 0xFF) : 0x1FF, in);
            }
        }
        __syncthreads();

        // parallel threshold: suffix scan over bins (descending digit order)
        unsigned v = 0, add = 0;
        if (tid < 256) {
            v = hist[255 - tid];
            #pragma unroll
            for (int off = 1; off < 32; off <<= 1) {
                unsigned n = __shfl_up_sync(FULLM, v, off);
                if ((tid & 31) >= off) v += n;
            }
            if ((tid & 31) == 31) ctr[8 + (tid >> 5)] = v;
        }
        __syncthreads();
        if (tid < 256) {
            for (int w = 0; w < (tid >> 5); w++) add += ctr[8 + w];
            if ((unsigned)defCnt + v + add > (unsigned)TOPK)
                atomicMin(&ctr[2], (unsigned)tid);
            if (tid == 255) ctr[5] = v + add;     // grand total matching prefix
        }
        __syncthreads();
        unsigned kmin = ctr[2];
        if (kmin == 256) {                         // everything fits (<= TOPK)
            C = prefix;
            break;
        }
        if (tid == kmin) { ctr[3] = v + add; ctr[4] = hist[255 - (int)tid]; }
        __syncthreads();
        int t      = 255 - (int)kmin;
        int newDef = defCnt + (int)ctr[3] - (int)ctr[4];
        int nc     = (int)ctr[4];
        if (newDef + nc <= 256) {
            C = prefix | ((unsigned long long)t << shift);
            break;
        }
        defCnt = newDef;
        prefix |= ((unsigned long long)t << shift);
        shift -= 8;
        __syncthreads();
    }

    // ---------------- collect all keys >= C (<= 256 of them) ---------------
    if (tid == 0) ctr[0] = 0;
    __syncthreads();
    for (int it = 0; it <= FULL_IT; it++) {
        int i = it * NT + tid;
        bool valid = (it < FULL_IT) || (tid < TAIL);
        uint4 m4 = valid ? col4[i] : make_uint4(0, 0, 0, 0);
        #pragma unroll
        for (int q = 0; q < 4; q++) {
            unsigned m = (q == 0) ? m4.x : (q == 1) ? m4.y : (q == 2) ? m4.z : m4.w;
            unsigned idx = (unsigned)(i * 4 + q);
            unsigned long long key = ((unsigned long long)m << 32) | (unsigned)(~idx);
            bool p = valid && (key >= C);
            unsigned bal = __ballot_sync(FULLM, p);
            int lane = tid & 31;
            int base = 0;
            if (lane == 0 && bal) base = (int)atomicAdd(&ctr[0], (unsigned)__popc(bal));
            base = __shfl_sync(FULLM, base, 0);
            if (p) {
                int pos = base + __popc(bal & ((1u << lane) - 1u));
                if (pos < 256) defs[pos] = key;
            }
        }
    }
    __syncthreads();
    int cnt = (int)ctr[0];
    for (int i = cnt + tid; i < 256; i += NT) defs[i] = 0ull;
    __syncthreads();

    // ---------------- hybrid bitonic sort of 256 u64 (ascending) -----------
    {
        unsigned long long a = (tid < 256) ? defs[tid] : 0ull;
        for (int k = 2; k <= 256; k <<= 1) {
            for (int j = k >> 1; j > 0; j >>= 1) {
                if (j >= 32) {
                    if (tid < 256) defs[tid] = a;
                    __syncthreads();
                    if (tid < 256) {
                        unsigned long long bb = defs[tid ^ j];
                        bool keep_small = (((tid & j) == 0) == ((tid & k) == 0));
                        a = ((a < bb) == keep_small) ? a : bb;
                    }
                    __syncthreads();
                } else {
                    if (tid < 256) {
                        unsigned lo = (unsigned)a, hi2 = (unsigned)(a >> 32);
                        unsigned plo = __shfl_xor_sync(FULLM, lo, j);
                        unsigned phi = __shfl_xor_sync(FULLM, hi2, j);
                        unsigned long long bb = ((unsigned long long)phi << 32) | plo;
                        bool keep_small = (((tid & j) == 0) == ((tid & k) == 0));
                        a = ((a < bb) == keep_small) ? a : bb;
                    }
                }
            }
        }
        if (tid < 256) defs[tid] = a;
        __syncthreads();
    }

    // ---------------- decode top-200 ---------------------------------------
    if (tid < TOPK) {
        unsigned long long key = defs[255 - tid];
        if (key) {
            unsigned m   = (unsigned)(key >> 32);
            unsigned idx = ~((unsigned)key);
            float sv = unmapf(m);
            float4 l  = __ldg((const float4*)loc + ((size_t)b * NP + idx));
            float4 pr = __ldg((const float4*)prior + idx);
            float cx = pr.x + l.x * 0.1f * pr.z;
            float cy = pr.y + l.y * 0.1f * pr.w;
            float w  = pr.z * expf(l.z * 0.2f);
            float h  = pr.w * expf(l.w * 0.2f);
            float x1 = cx - w * 0.5f;
            float y1 = cy - h * 0.5f;
            float x2 = x1 + w;
            float y2 = y1 + h;
            boxs[tid]  = make_float4(x1, y1, x2, y2);
            areas[tid] = (x2 - x1) * (y2 - y1);
            scores[tid] = sv;
        } else {
            boxs[tid]  = make_float4(0.f, 0.f, 0.f, 0.f);
            areas[tid] = 0.f;
            scores[tid] = -1.0f;
        }
    }
    for (int i = tid; i < TOPK * 8; i += NT) rows[i] = 0;
    __syncthreads();

    // ---------------- IoU bit-matrix: warp per (k-word, j-chunk) -----------
    {
        const int wid = tid >> 5, lane = tid & 31;
        for (int tt = wid; tt < 28; tt += 16) {
            int w = 0;
            while ((w + 1) * (w + 2) / 2 <= tt) w++;
            int jc = tt - w * (w + 1) / 2;
            int k = w * 32 + lane;
            bool kv = k < TOPK;
            float4 bk = kv ? boxs[k] : make_float4(0.f, 0.f, 0.f, 0.f);
            float  ak = kv ? areas[k] : 0.f;
            int j0 = jc * 32, j1 = min(j0 + 32, TOPK);
            for (int j = j0; j < j1; j++) {
                float4 bj = boxs[j];
                float  aj = areas[j];
                bool hit = false;
                if (kv && k > j) {
                    float xx1 = fmaxf(bj.x, bk.x);
                    float yy1 = fmaxf(bj.y, bk.y);
                    float xx2 = fminf(bj.z, bk.z);
                    float yy2 = fminf(bj.w, bk.w);
                    float iw = fmaxf(xx2 - xx1, 0.0f);
                    float ih = fmaxf(yy2 - yy1, 0.0f);
                    float inter = iw * ih;
                    float uni = aj + ak - inter;
                    float iou = inter / uni;
                    hit = iou > 0.45f;
                }
                unsigned bal = __ballot_sync(FULLM, hit);
                if (lane == 0 && bal) rows[j * 8 + w] = bal;
            }
        }
    }
    __syncthreads();

    // per-word validity + has-row masks (warps 0..6 cover j 0..223)
    if (tid < 224) {
        int j = tid;
        bool val = (j < TOPK) && (scores[j] > 0.01f);
        unsigned r = 0;
        if (j < TOPK) {
            uint4 r1 = *(const uint4*)&rows[j * 8];
            uint4 r2 = *(const uint4*)&rows[j * 8 + 4];
            r = r1.x | r1.y | r1.z | r1.w | r2.x | r2.y | r2.z;
        }
        unsigned vb = __ballot_sync(FULLM, val);
        unsigned hb = __ballot_sync(FULLM, r != 0);
        if ((tid & 31) == 0) { validw[tid >> 5] = vb; hasroww[tid >> 5] = hb; }
    }
    __syncthreads();

    // ---------------- serial greedy (bit ops; LDS only on overlapping boxes)
    if (tid == 0) {
        unsigned sup[7] = {0, 0, 0, 0, 0, 0, 0};
        #pragma unroll
        for (int w = 0; w < 7; w++) {
            unsigned kwv = 0;
            unsigned rowm = hasroww[w];
            unsigned pend = validw[w] & ~sup[w];
            while (pend) {
                unsigned r = pend & rowm;
                if (!r) { kwv |= pend; break; }       // rest have no rows
                int bsh = __ffs(r) - 1;
                unsigned below = (1u << bsh) - 1u;
                kwv |= pend & below;                  // batch-accept no-row bits
                kwv |= 1u << bsh;                     // accept the row bit
                int j = w * 32 + bsh;
                uint4 r1 = *(const uint4*)&rows[j * 8];
                uint4 r2 = *(const uint4*)&rows[j * 8 + 4];
                sup[0] |= r1.x; sup[1] |= r1.y; sup[2] |= r1.z; sup[3] |= r1.w;
                sup[4] |= r2.x; sup[5] |= r2.y; sup[6] |= r2.z;
                unsigned above = ~((below << 1) | 1u);
                pend = validw[w] & ~sup[w] & above;
            }
            keepw[w] = kwv;
        }
    }
    __syncthreads();

    // ---------------- compact & write --------------------------------------
    if (tid < TOPK) {
        int w = tid >> 5, bs = tid & 31;
        unsigned kwv = keepw[w];
        if ((kwv >> bs) & 1u) {
            int pos = 0;
            #pragma unroll
            for (int ww = 0; ww < 7; ww++) if (ww < w) pos += __popc(keepw[ww]);
            pos += __popc(kwv & ((1u << bs) - 1u));
            float4 bx = boxs[tid];
            float* row = outBase + pos * 5;
            row[0] = scores[tid];
            row[1] = bx.x;
            row[2] = bx.y;
            row[3] = bx.z;
            row[4] = bx.w;
        }
    }
}

// ---------------------------------------------------------------------------
extern "C" void kernel_launch(void* const* d_in, const int* in_sizes, int n_in,
                              void* d_out, int out_size) {
    const float* loc   = (const float*)d_in[0];
    const float* conf  = (const float*)d_in[1];
    const float* prior = (const float*)d_in[2];
    float* out = (float*)d_out;

    const int nt = (NP + TP - 1) / TP;          // 18
    transpose_kernel<<<NB * nt, 256>>>(conf);
    select_kernel<<<NB * NC, NT>>>(loc, prior, out);
}

// round 4
// speedup vs baseline: 2.2339x; 1.0385x over previous
#include <cuda_runtime.h>
#include <math.h>

#define NB   32
#define NP   8732
#define NC   21
#define TOPK 200
#define NT   512
#define NP4  (NP / 4)      // 2183
#define FULLM 0xFFFFFFFFu

// Transposed, thresholded, order-mapped confidences: key32[b][c][p]
__device__ unsigned g_confT[(size_t)NB * NC * NP];

// ---------------------------------------------------------------------------
// Kernel 1: transpose + threshold + monotonic map, vectorized stores
// ---------------------------------------------------------------------------
#define TP  512
#define S2S 516            // padded row stride (floats): 4-aligned for LDS.128
__global__ void transpose_kernel(const float* __restrict__ conf) {
    __shared__ float s2[NC * S2S];          // 43.3 KB
    const int nt  = (NP + TP - 1) / TP;     // 18
    const int b   = blockIdx.x / nt;
    const int t   = blockIdx.x % nt;
    const int p0  = t * TP;
    const int np  = min(TP, NP - p0);       // 512 or 28 (both mult of 4)
    const float* src = conf + ((size_t)b * NP + p0) * NC;
    const int n  = np * NC;                 // multiple of 4
    const int nv = n >> 2;
    const float4* src4 = (const float4*)src;

    for (int i = threadIdx.x; i < nv; i += blockDim.x) {
        float4 v = src4[i];
        int li = i * 4;
        #pragma unroll
        for (int q = 0; q < 4; q++) {
            int e = li + q;
            int p = e / NC;
            int c = e - p * NC;
            float f = (q == 0) ? v.x : (q == 1) ? v.y : (q == 2) ? v.z : v.w;
            s2[c * S2S + p] = f;
        }
    }
    __syncthreads();

    const int ng = np >> 2;                 // p-groups of 4
    for (int idx = threadIdx.x; idx < NC * ng; idx += blockDim.x) {
        int c = idx / ng;
        int g = idx - c * ng;
        int p = g * 4;
        float4 v = *(const float4*)&s2[c * S2S + p];
        uint4 o;
        {
            float sv = (v.x > 0.01f) ? v.x : -1.0f;
            unsigned u = __float_as_uint(sv);
            o.x = (u & 0x80000000u) ? ~u : (u | 0x80000000u);
        }
        {
            float sv = (v.y > 0.01f) ? v.y : -1.0f;
            unsigned u = __float_as_uint(sv);
            o.y = (u & 0x80000000u) ? ~u : (u | 0x80000000u);
        }
        {
            float sv = (v.z > 0.01f) ? v.z : -1.0f;
            unsigned u = __float_as_uint(sv);
            o.z = (u & 0x80000000u) ? ~u : (u | 0x80000000u);
        }
        {
            float sv = (v.w > 0.01f) ? v.w : -1.0f;
            unsigned u = __float_as_uint(sv);
            o.w = (u & 0x80000000u) ? ~u : (u | 0x80000000u);
        }
        *(uint4*)(g_confT + ((size_t)b * NC + c) * NP + p0 + p) = o;
    }
}

// ---------------------------------------------------------------------------
__device__ __forceinline__ float unmapf(unsigned m) {
    unsigned u = (m & 0x80000000u) ? (m ^ 0x80000000u) : ~m;
    return __uint_as_float(u);
}

// warp-aggregated histogram add (all 32 lanes converged)
__device__ __forceinline__ void aggHist(unsigned* hist, int d, bool in) {
    unsigned mm = __match_any_sync(FULLM, d);
    int lane = threadIdx.x & 31;
    if (in && lane == (__ffs(mm) - 1))
        atomicAdd(&hist[d], (unsigned)__popc(mm));
}

__global__ __launch_bounds__(NT, 3)
void select_kernel(const float* __restrict__ loc,
                   const float* __restrict__ prior,
                   float* __restrict__ out) {
    const int blk = blockIdx.x;
    const int b   = blk / NC;
    const int c   = blk % NC;
    const int tid = threadIdx.x;
    const int lane = tid & 31;
    const int wid  = tid >> 5;
    float* outBase = out + (size_t)blk * (TOPK * 5);

    // zero output slab (float4; 1000 floats -> 250 vec4, base 4000B-aligned)
    {
        float4* ob4 = (float4*)outBase;
        for (int i = tid; i < (TOPK * 5) / 4; i += NT)
            ob4[i] = make_float4(0.f, 0.f, 0.f, 0.f);
    }
    if (c == 0) return;

    __shared__ unsigned hist[8192];          // 32 KB
    __shared__ unsigned ctr[8];
    __shared__ unsigned warpSums[16];
    __shared__ unsigned long long defs[512]; // 4 KB
    __shared__ float4   boxs[TOPK];
    __shared__ float    areas[TOPK];
    __shared__ float    scores[TOPK];
    __shared__ unsigned rows[TOPK * 8];
    __shared__ unsigned keepw[8];
    __shared__ unsigned validw[8];
    __shared__ unsigned hasroww[8];

    const uint4* col4 = (const uint4*)(g_confT + (size_t)blk * NP);
    const int FULL_IT = NP4 / NT;           // 4
    const int TAIL    = NP4 - FULL_IT * NT; // 135

    // ---------------- round 0: 13-bit histogram (32-bit work only) ---------
    {
        uint4* h4 = (uint4*)hist;
        for (int i = tid; i < 2048; i += NT) h4[i] = make_uint4(0, 0, 0, 0);
    }
    __syncthreads();

    for (int it = 0; it <= FULL_IT; it++) {
        int i = it * NT + tid;
        bool valid = (it < FULL_IT) || (tid < TAIL);
        uint4 m4 = valid ? col4[i] : make_uint4(0, 0, 0, 0);
        aggHist(hist, valid ? (int)(m4.x >> 19) : 0x3FFF, valid);
        aggHist(hist, valid ? (int)(m4.y >> 19) : 0x3FFF, valid);
        aggHist(hist, valid ? (int)(m4.z >> 19) : 0x3FFF, valid);
        aggHist(hist, valid ? (int)(m4.w >> 19) : 0x3FFF, valid);
    }
    __syncthreads();

    // ---------------- parallel threshold over 8192 bins (descending) ------
    {
        int hi = 8191 - (tid << 4);          // thread covers digits hi..hi-15
        unsigned lsum = 0;
        #pragma unroll
        for (int q = 0; q < 16; q++) lsum += hist[hi - q];
        unsigned inc = lsum;
        #pragma unroll
        for (int off = 1; off < 32; off <<= 1) {
            unsigned nn = __shfl_up_sync(FULLM, inc, off);
            if (lane >= off) inc += nn;
        }
        if (lane == 31) warpSums[wid] = inc;
        __syncthreads();
        if (wid == 0) {
            unsigned v = (lane < 16) ? warpSums[lane] : 0;
            #pragma unroll
            for (int off = 1; off < 16; off <<= 1) {
                unsigned nn = __shfl_up_sync(FULLM, v, off);
                if (lane >= off) v += nn;
            }
            if (lane < 16) warpSums[lane] = v;   // inclusive warp prefix
        }
        __syncthreads();
        unsigned ex = (wid ? warpSums[wid - 1] : 0) + inc - lsum;
        if (ex <= TOPK && ex + lsum > TOPK) {    // unique crossing thread
            unsigned acc = ex;
            #pragma unroll
            for (int q = 0; q < 16; q++) {
                unsigned h = hist[hi - q];
                if (acc + h > TOPK) {
                    ctr[1] = (unsigned)(hi - q);  // t0
                    ctr[2] = acc;                 // defCnt
                    ctr[3] = h;                   // boundary bin count
                    break;
                }
                acc += h;
            }
        }
    }
    __syncthreads();

    unsigned long long C;
    {
        unsigned t0 = ctr[1];
        int defCnt  = (int)ctr[2];
        int nc      = (int)ctr[3];

        if (defCnt + nc <= 512) {
            C = (unsigned long long)t0 << 51;     // fast path (always on uniform data)
        } else {
            // -------- fallback: generic 8-bit rounds on 64-bit keys --------
            unsigned long long prefix = (unsigned long long)t0 << 51;
            int shift = 43;
            while (true) {
                if (tid < 64) ((uint4*)hist)[tid] = make_uint4(0, 0, 0, 0);
                if (tid == 0) ctr[4] = 256;
                __syncthreads();
                for (int it = 0; it <= FULL_IT; it++) {
                    int i = it * NT + tid;
                    bool valid = (it < FULL_IT) || (tid < TAIL);
                    uint4 m4 = valid ? col4[i] : make_uint4(0, 0, 0, 0);
                    #pragma unroll
                    for (int q = 0; q < 4; q++) {
                        unsigned m = (q == 0) ? m4.x : (q == 1) ? m4.y : (q == 2) ? m4.z : m4.w;
                        unsigned idx = (unsigned)(i * 4 + q);
                        unsigned long long key =
                            ((unsigned long long)m << 32) | (unsigned)(~idx);
                        unsigned long long hi64 = (key ^ prefix) >> shift;
                        bool in = valid && ((hi64 >> 8) == 0);
                        aggHist(hist, in ? (int)(hi64 & 0xFF) : 0x1FF, in);
                    }
                }
                __syncthreads();
                unsigned v = 0, add = 0;
                if (tid < 256) {
                    v = hist[255 - tid];
                    #pragma unroll
                    for (int off = 1; off < 32; off <<= 1) {
                        unsigned nn = __shfl_up_sync(FULLM, v, off);
                        if (lane >= off) v += nn;
                    }
                    if (lane == 31) warpSums[wid] = v;
                }
                __syncthreads();
                if (tid < 256) {
                    for (int w = 0; w < wid; w++) add += warpSums[w];
                    if ((unsigned)defCnt + v + add > (unsigned)TOPK)
                        atomicMin(&ctr[4], (unsigned)tid);
                }
                __syncthreads();
                unsigned kmin = ctr[4];
                if (tid == (int)kmin) { ctr[5] = v + add; ctr[6] = hist[255 - (int)kmin]; }
                __syncthreads();
                int t      = 255 - (int)kmin;
                int newDef = defCnt + (int)ctr[5] - (int)ctr[6];
                int bnc    = (int)ctr[6];
                if (newDef + bnc <= 512 || shift == 3) {
                    C = prefix | ((unsigned long long)t << shift);
                    break;
                }
                defCnt = newDef;
                prefix |= ((unsigned long long)t << shift);
                shift -= 8;
                __syncthreads();
            }
        }
    }

    // ---------------- collect all keys >= C (<= 512) ------------------------
    if (tid == 0) ctr[0] = 0;
    __syncthreads();
    for (int it = 0; it <= FULL_IT; it++) {
        int i = it * NT + tid;
        bool valid = (it < FULL_IT) || (tid < TAIL);
        uint4 m4 = valid ? col4[i] : make_uint4(0, 0, 0, 0);
        #pragma unroll
        for (int q = 0; q < 4; q++) {
            unsigned m = (q == 0) ? m4.x : (q == 1) ? m4.y : (q == 2) ? m4.z : m4.w;
            unsigned idx = (unsigned)(i * 4 + q);
            unsigned long long key = ((unsigned long long)m << 32) | (unsigned)(~idx);
            bool p = valid && (key >= C);
            unsigned bal = __ballot_sync(FULLM, p);
            int base = 0;
            if (lane == 0 && bal) base = (int)atomicAdd(&ctr[0], (unsigned)__popc(bal));
            base = __shfl_sync(FULLM, base, 0);
            if (p) {
                int pos = base + __popc(bal & ((1u << lane) - 1u));
                if (pos < 512) defs[pos] = key;
            }
        }
    }
    __syncthreads();
    int cnt = min((int)ctr[0], 512);
    for (int i = cnt + tid; i < 512; i += NT) defs[i] = 0ull;
    __syncthreads();

    // ---------------- hybrid bitonic sort of 512 u64 (ascending) -----------
    {
        unsigned long long a = defs[tid];
        for (int k = 2; k <= 512; k <<= 1) {
            for (int j = k >> 1; j > 0; j >>= 1) {
                if (j >= 32) {
                    defs[tid] = a;
                    __syncthreads();
                    unsigned long long bb = defs[tid ^ j];
                    bool ks = (((tid & j) == 0) == ((tid & k) == 0));
                    a = ((a < bb) == ks) ? a : bb;
                    __syncthreads();
                } else {
                    unsigned lo = (unsigned)a, hi2 = (unsigned)(a >> 32);
                    unsigned plo = __shfl_xor_sync(FULLM, lo, j);
                    unsigned phi = __shfl_xor_sync(FULLM, hi2, j);
                    unsigned long long bb = ((unsigned long long)phi << 32) | plo;
                    bool ks = (((tid & j) == 0) == ((tid & k) == 0));
                    a = ((a < bb) == ks) ? a : bb;
                }
            }
        }
        defs[tid] = a;
        __syncthreads();
    }

    // ---------------- decode top-200 ---------------------------------------
    if (tid < TOPK) {
        unsigned long long key = defs[511 - tid];
        if (key) {
            unsigned m   = (unsigned)(key >> 32);
            unsigned idx = ~((unsigned)key);
            float sv = unmapf(m);
            float4 l  = __ldg((const float4*)loc + ((size_t)b * NP + idx));
            float4 pr = __ldg((const float4*)prior + idx);
            float cx = pr.x + l.x * 0.1f * pr.z;
            float cy = pr.y + l.y * 0.1f * pr.w;
            float w  = pr.z * expf(l.z * 0.2f);
            float h  = pr.w * expf(l.w * 0.2f);
            float x1 = cx - w * 0.5f;
            float y1 = cy - h * 0.5f;
            float x2 = x1 + w;
            float y2 = y1 + h;
            boxs[tid]  = make_float4(x1, y1, x2, y2);
            areas[tid] = (x2 - x1) * (y2 - y1);
            scores[tid] = sv;
        } else {
            boxs[tid]  = make_float4(0.f, 0.f, 0.f, 0.f);
            areas[tid] = 0.f;
            scores[tid] = -1.0f;
        }
    }
    for (int i = tid; i < TOPK * 8; i += NT) rows[i] = 0;
    __syncthreads();

    // ---------------- IoU bit-matrix: warp per (k-word, j-chunk) -----------
    {
        for (int tt = wid; tt < 28; tt += 16) {
            int w = 0;
            while ((w + 1) * (w + 2) / 2 <= tt) w++;
            int jc = tt - w * (w + 1) / 2;
            int k = w * 32 + lane;
            bool kv = k < TOPK;
            float4 bk = kv ? boxs[k] : make_float4(0.f, 0.f, 0.f, 0.f);
            float  ak = kv ? areas[k] : 0.f;
            int j0 = jc * 32, j1 = min(j0 + 32, TOPK);
            for (int j = j0; j < j1; j++) {
                float4 bj = boxs[j];
                float  aj = areas[j];
                bool hit = false;
                if (kv && k > j) {
                    float xx1 = fmaxf(bj.x, bk.x);
                    float yy1 = fmaxf(bj.y, bk.y);
                    float xx2 = fminf(bj.z, bk.z);
                    float yy2 = fminf(bj.w, bk.w);
                    float iw = fmaxf(xx2 - xx1, 0.0f);
                    float ih = fmaxf(yy2 - yy1, 0.0f);
                    float inter = iw * ih;
                    float uni = aj + ak - inter;
                    float iou = inter / uni;
                    hit = iou > 0.45f;
                }
                unsigned bal = __ballot_sync(FULLM, hit);
                if (lane == 0 && bal) rows[j * 8 + w] = bal;
            }
        }
    }
    __syncthreads();

    // per-word validity + has-row masks
    if (tid < 224) {
        int j = tid;
        bool val = (j < TOPK) && (scores[j] > 0.01f);
        unsigned r = 0;
        if (j < TOPK) {
            uint4 r1 = *(const uint4*)&rows[j * 8];
            uint4 r2 = *(const uint4*)&rows[j * 8 + 4];
            r = r1.x | r1.y | r1.z | r1.w | r2.x | r2.y | r2.z;
        }
        unsigned vb = __ballot_sync(FULLM, val);
        unsigned hb = __ballot_sync(FULLM, r != 0);
        if (lane == 0) { validw[wid] = vb; hasroww[wid] = hb; }
    }
    __syncthreads();

    // ---------------- serial greedy (bit ops) -------------------------------
    if (tid == 0) {
        unsigned sup[7] = {0, 0, 0, 0, 0, 0, 0};
        #pragma unroll
        for (int w = 0; w < 7; w++) {
            unsigned kwv = 0;
            unsigned rowm = hasroww[w];
            unsigned pend = validw[w] & ~sup[w];
            while (pend) {
                unsigned r = pend & rowm;
                if (!r) { kwv |= pend; break; }
                int bsh = __ffs(r) - 1;
                unsigned below = (1u << bsh) - 1u;
                kwv |= pend & below;
                kwv |= 1u << bsh;
                int j = w * 32 + bsh;
                uint4 r1 = *(const uint4*)&rows[j * 8];
                uint4 r2 = *(const uint4*)&rows[j * 8 + 4];
                sup[0] |= r1.x; sup[1] |= r1.y; sup[2] |= r1.z; sup[3] |= r1.w;
                sup[4] |= r2.x; sup[5] |= r2.y; sup[6] |= r2.z;
                unsigned above = ~((below << 1) | 1u);
                pend = validw[w] & ~sup[w] & above;
            }
            keepw[w] = kwv;
        }
    }
    __syncthreads();

    // ---------------- compact & write ---------------------------------------
    if (tid < TOPK) {
        int w = tid >> 5, bs = tid & 31;
        unsigned kwv = keepw[w];
        if ((kwv >> bs) & 1u) {
            int pos = 0;
            #pragma unroll
            for (int ww = 0; ww < 7; ww++) if (ww < w) pos += __popc(keepw[ww]);
            pos += __popc(kwv & ((1u << bs) - 1u));
            float4 bx = boxs[tid];
            float* row = outBase + pos * 5;
            row[0] = scores[tid];
            row[1] = bx.x;
            row[2] = bx.y;
            row[3] = bx.z;
            row[4] = bx.w;
        }
    }
}

// ---------------------------------------------------------------------------
extern "C" void kernel_launch(void* const* d_in, const int* in_sizes, int n_in,
                              void* d_out, int out_size) {
    const float* loc   = (const float*)d_in[0];
    const float* conf  = (const float*)d_in[1];
    const float* prior = (const float*)d_in[2];
    float* out = (float*)d_out;

    const int nt = (NP + TP - 1) / TP;          // 18
    transpose_kernel<<<NB * nt, 256>>>(conf);
    select_kernel<<<NB * NC, NT>>>(loc, prior, out);
}

// round 5
// speedup vs baseline: 2.2729x; 1.0174x over previous
#include <cuda_runtime.h>
#include <math.h>

#define NB   32
#define NP   8732
#define NC   21
#define TOPK 200
#define NT   512
#define NP4  (NP / 4)      // 2183
#define NBIN 8192
#define FULLM 0xFFFFFFFFu

// Transposed, thresholded, order-mapped confidences: key32[b][c][p]
__device__ unsigned g_confT[(size_t)NB * NC * NP];
// Per-(b,c) 13-bit histograms (zeroed each launch via memsetAsync)
__device__ unsigned g_hist[(size_t)NB * NC * NBIN];
// Per-(b,c) pivot: (t0 << 51) | overflow_flag(bit0)
__device__ unsigned long long g_pivot[NB * NC];

// ---------------------------------------------------------------------------
// Kernel 1: transpose + threshold + monotonic map + global histogram
// ---------------------------------------------------------------------------
#define TP  512
#define S2S 516
__global__ void transpose_kernel(const float* __restrict__ conf) {
    __shared__ float s2[NC * S2S];
    const int nt  = (NP + TP - 1) / TP;     // 18
    const int b   = blockIdx.x / nt;
    const int t   = blockIdx.x % nt;
    const int p0  = t * TP;
    const int np  = min(TP, NP - p0);
    const float* src = conf + ((size_t)b * NP + p0) * NC;
    const int n  = np * NC;
    const int nv = n >> 2;
    const float4* src4 = (const float4*)src;

    for (int i = threadIdx.x; i < nv; i += blockDim.x) {
        float4 v = src4[i];
        int li = i * 4;
        #pragma unroll
        for (int q = 0; q < 4; q++) {
            int e = li + q;
            int p = e / NC;
            int c = e - p * NC;
            float f = (q == 0) ? v.x : (q == 1) ? v.y : (q == 2) ? v.z : v.w;
            s2[c * S2S + p] = f;
        }
    }
    __syncthreads();

    const int ng = np >> 2;
    for (int idx = threadIdx.x; idx < NC * ng; idx += blockDim.x) {
        int c = idx / ng;
        int g = idx - c * ng;
        int p = g * 4;
        float4 v = *(const float4*)&s2[c * S2S + p];
        uint4 o;
        {
            float sv = (v.x > 0.01f) ? v.x : -1.0f;
            unsigned u = __float_as_uint(sv);
            o.x = (u & 0x80000000u) ? ~u : (u | 0x80000000u);
        }
        {
            float sv = (v.y > 0.01f) ? v.y : -1.0f;
            unsigned u = __float_as_uint(sv);
            o.y = (u & 0x80000000u) ? ~u : (u | 0x80000000u);
        }
        {
            float sv = (v.z > 0.01f) ? v.z : -1.0f;
            unsigned u = __float_as_uint(sv);
            o.z = (u & 0x80000000u) ? ~u : (u | 0x80000000u);
        }
        {
            float sv = (v.w > 0.01f) ? v.w : -1.0f;
            unsigned u = __float_as_uint(sv);
            o.w = (u & 0x80000000u) ? ~u : (u | 0x80000000u);
        }
        *(uint4*)(g_confT + ((size_t)b * NC + c) * NP + p0 + p) = o;
        if (c != 0) {
            unsigned* hb = g_hist + ((size_t)b * NC + c) * NBIN;
            atomicAdd(&hb[o.x >> 19], 1u);
            atomicAdd(&hb[o.y >> 19], 1u);
            atomicAdd(&hb[o.z >> 19], 1u);
            atomicAdd(&hb[o.w >> 19], 1u);
        }
    }
}

// ---------------------------------------------------------------------------
// Kernel 2: per-(b,c) pivot from histogram (descending cumulative > TOPK)
// ---------------------------------------------------------------------------
__global__ __launch_bounds__(256)
void pivot_kernel() {
    const int blk = blockIdx.x;
    if (blk % NC == 0) return;
    const int tid = threadIdx.x;
    const int lane = tid & 31;
    const int wid  = tid >> 5;
    __shared__ unsigned warpSums[8];
    __shared__ unsigned res[4];           // t0, defCnt, nc

    const unsigned* h = g_hist + (size_t)blk * NBIN;
    const int hi = 8191 - (tid << 5);     // thread covers bins hi .. hi-31 (descending)

    unsigned bins[32];
    {
        const uint4* h4 = (const uint4*)(h + (hi - 31));
        #pragma unroll
        for (int q = 0; q < 8; q++) {
            uint4 v = h4[q];
            bins[q * 4 + 0] = v.x; bins[q * 4 + 1] = v.y;
            bins[q * 4 + 2] = v.z; bins[q * 4 + 3] = v.w;
        }
    }
    unsigned lsum = 0;
    #pragma unroll
    for (int q = 0; q < 32; q++) lsum += bins[q];

    unsigned inc = lsum;
    #pragma unroll
    for (int off = 1; off < 32; off <<= 1) {
        unsigned nn = __shfl_up_sync(FULLM, inc, off);
        if (lane >= off) inc += nn;
    }
    if (lane == 31) warpSums[wid] = inc;
    __syncthreads();
    unsigned wadd = 0;
    for (int w = 0; w < wid; w++) wadd += warpSums[w];
    unsigned ex = wadd + inc - lsum;      // exclusive prefix (descending)

    if (ex <= TOPK && ex + lsum > TOPK) { // unique crossing thread
        unsigned acc = ex;
        #pragma unroll
        for (int q = 0; q < 32; q++) {
            unsigned hv = bins[31 - q];   // bins[31-q] = bin (hi - q)
            if (acc + hv > TOPK) {
                res[0] = (unsigned)(hi - q);
                res[1] = acc;
                res[2] = hv;
                break;
            }
            acc += hv;
        }
    }
    __syncthreads();
    if (tid == 0) {
        unsigned long long C = (unsigned long long)res[0] << 51;
        if (res[1] + res[2] > 512u) C |= 1ull;   // overflow flag
        g_pivot[blk] = C;
    }
}

// ---------------------------------------------------------------------------
__device__ __forceinline__ float unmapf(unsigned m) {
    unsigned u = (m & 0x80000000u) ? (m ^ 0x80000000u) : ~m;
    return __uint_as_float(u);
}

// ---------------------------------------------------------------------------
// Kernel 3: collect >= C, sort, decode, NMS, write
// ---------------------------------------------------------------------------
__global__ __launch_bounds__(NT, 4)
void select_kernel(const float* __restrict__ loc,
                   const float* __restrict__ prior,
                   float* __restrict__ out) {
    const int blk = blockIdx.x;
    const int b   = blk / NC;
    const int c   = blk % NC;
    const int tid = threadIdx.x;
    const int lane = tid & 31;
    const int wid  = tid >> 5;
    float* outBase = out + (size_t)blk * (TOPK * 5);

    {
        float4* ob4 = (float4*)outBase;
        for (int i = tid; i < (TOPK * 5) / 4; i += NT)
            ob4[i] = make_float4(0.f, 0.f, 0.f, 0.f);
    }
    if (c == 0) return;

    __shared__ unsigned ctr[8];
    __shared__ unsigned long long defs[512];
    __shared__ float4   boxs[TOPK];
    __shared__ float    areas[TOPK];
    __shared__ float    scores[TOPK];
    __shared__ unsigned rows[TOPK * 8];
    __shared__ unsigned keepw[8];
    __shared__ unsigned validw[8];
    __shared__ unsigned hasroww[8];

    const uint4* col4 = (const uint4*)(g_confT + (size_t)blk * NP);
    const int FULL_IT = NP4 / NT;           // 4
    const int TAIL    = NP4 - FULL_IT * NT; // 135

    unsigned long long pv = g_pivot[blk];
    unsigned long long C  = pv & ~1ull;

    if (pv & 1ull) {
        // ------- rare exact fallback: bitwise search for the 200th key -----
        unsigned long long Cp = (pv >> 51) << 51;
        for (int bit = 50; bit >= 0; bit--) {
            unsigned long long trial = Cp | (1ull << bit);
            if (tid == 0) ctr[7] = 0;
            __syncthreads();
            unsigned wcnt = 0;
            for (int it = 0; it <= FULL_IT; it++) {
                int i = it * NT + tid;
                bool valid = (it < FULL_IT) || (tid < TAIL);
                uint4 m4 = valid ? col4[i] : make_uint4(0, 0, 0, 0);
                #pragma unroll
                for (int q = 0; q < 4; q++) {
                    unsigned m = (q == 0) ? m4.x : (q == 1) ? m4.y : (q == 2) ? m4.z : m4.w;
                    unsigned idx = (unsigned)(i * 4 + q);
                    unsigned long long key =
                        ((unsigned long long)m << 32) | (unsigned)(~idx);
                    wcnt += __popc(__ballot_sync(FULLM, valid && key >= trial));
                }
            }
            if (lane == 0) atomicAdd(&ctr[7], wcnt);
            __syncthreads();
            if (ctr[7] >= TOPK) Cp = trial;
            __syncthreads();
        }
        C = Cp;
    }

    // ---------------- collect all keys >= C (<= 512) ------------------------
    if (tid == 0) ctr[0] = 0;
    __syncthreads();
    for (int it = 0; it <= FULL_IT; it++) {
        int i = it * NT + tid;
        bool valid = (it < FULL_IT) || (tid < TAIL);
        uint4 m4 = valid ? col4[i] : make_uint4(0, 0, 0, 0);
        #pragma unroll
        for (int q = 0; q < 4; q++) {
            unsigned m = (q == 0) ? m4.x : (q == 1) ? m4.y : (q == 2) ? m4.z : m4.w;
            unsigned idx = (unsigned)(i * 4 + q);
            unsigned long long key = ((unsigned long long)m << 32) | (unsigned)(~idx);
            bool p = valid && (key >= C);
            unsigned bal = __ballot_sync(FULLM, p);
            int base = 0;
            if (lane == 0 && bal) base = (int)atomicAdd(&ctr[0], (unsigned)__popc(bal));
            base = __shfl_sync(FULLM, base, 0);
            if (p) {
                int pos = base + __popc(bal & ((1u << lane) - 1u));
                if (pos < 512) defs[pos] = key;
            }
        }
    }
    __syncthreads();
    int cnt = min((int)ctr[0], 512);
    for (int i = cnt + tid; i < 512; i += NT) defs[i] = 0ull;
    __syncthreads();

    // ---------------- hybrid bitonic sort of 512 u64 (ascending) -----------
    {
        unsigned long long a = defs[tid];
        for (int k = 2; k <= 512; k <<= 1) {
            for (int j = k >> 1; j > 0; j >>= 1) {
                if (j >= 32) {
                    defs[tid] = a;
                    __syncthreads();
                    unsigned long long bb = defs[tid ^ j];
                    bool ks = (((tid & j) == 0) == ((tid & k) == 0));
                    a = ((a < bb) == ks) ? a : bb;
                    __syncthreads();
                } else {
                    unsigned lo = (unsigned)a, hi2 = (unsigned)(a >> 32);
                    unsigned plo = __shfl_xor_sync(FULLM, lo, j);
                    unsigned phi = __shfl_xor_sync(FULLM, hi2, j);
                    unsigned long long bb = ((unsigned long long)phi << 32) | plo;
                    bool ks = (((tid & j) == 0) == ((tid & k) == 0));
                    a = ((a < bb) == ks) ? a : bb;
                }
            }
        }
        defs[tid] = a;
        __syncthreads();
    }

    // ---------------- decode top-200 ---------------------------------------
    if (tid < TOPK) {
        unsigned long long key = defs[511 - tid];
        if (key) {
            unsigned m   = (unsigned)(key >> 32);
            unsigned idx = ~((unsigned)key);
            float sv = unmapf(m);
            float4 l  = __ldg((const float4*)loc + ((size_t)b * NP + idx));
            float4 pr = __ldg((const float4*)prior + idx);
            float cx = pr.x + l.x * 0.1f * pr.z;
            float cy = pr.y + l.y * 0.1f * pr.w;
            float w  = pr.z * expf(l.z * 0.2f);
            float h  = pr.w * expf(l.w * 0.2f);
            float x1 = cx - w * 0.5f;
            float y1 = cy - h * 0.5f;
            float x2 = x1 + w;
            float y2 = y1 + h;
            boxs[tid]  = make_float4(x1, y1, x2, y2);
            areas[tid] = (x2 - x1) * (y2 - y1);
            scores[tid] = sv;
        } else {
            boxs[tid]  = make_float4(0.f, 0.f, 0.f, 0.f);
            areas[tid] = 0.f;
            scores[tid] = -1.0f;
        }
    }
    for (int i = tid; i < TOPK * 8; i += NT) rows[i] = 0;
    __syncthreads();

    // ---------------- IoU bit-matrix: warp per (k-word, j-chunk) -----------
    {
        for (int tt = wid; tt < 28; tt += 16) {
            int w = 0;
            while ((w + 1) * (w + 2) / 2 <= tt) w++;
            int jc = tt - w * (w + 1) / 2;
            int k = w * 32 + lane;
            bool kv = k < TOPK;
            float4 bk = kv ? boxs[k] : make_float4(0.f, 0.f, 0.f, 0.f);
            float  ak = kv ? areas[k] : 0.f;
            int j0 = jc * 32, j1 = min(j0 + 32, TOPK);
            for (int j = j0; j < j1; j++) {
                float4 bj = boxs[j];
                float  aj = areas[j];
                bool hit = false;
                if (kv && k > j) {
                    float xx1 = fmaxf(bj.x, bk.x);
                    float yy1 = fmaxf(bj.y, bk.y);
                    float xx2 = fminf(bj.z, bk.z);
                    float yy2 = fminf(bj.w, bk.w);
                    float iw = fmaxf(xx2 - xx1, 0.0f);
                    float ih = fmaxf(yy2 - yy1, 0.0f);
                    float inter = iw * ih;
                    float uni = aj + ak - inter;
                    float iou = inter / uni;
                    hit = iou > 0.45f;
                }
                unsigned bal = __ballot_sync(FULLM, hit);
                if (lane == 0 && bal) rows[j * 8 + w] = bal;
            }
        }
    }
    __syncthreads();

    if (tid < 224) {
        int j = tid;
        bool val = (j < TOPK) && (scores[j] > 0.01f);
        unsigned r = 0;
        if (j < TOPK) {
            uint4 r1 = *(const uint4*)&rows[j * 8];
            uint4 r2 = *(const uint4*)&rows[j * 8 + 4];
            r = r1.x | r1.y | r1.z | r1.w | r2.x | r2.y | r2.z;
        }
        unsigned vb = __ballot_sync(FULLM, val);
        unsigned hb = __ballot_sync(FULLM, r != 0);
        if (lane == 0) { validw[wid] = vb; hasroww[wid] = hb; }
    }
    __syncthreads();

    // ---------------- serial greedy (bit ops) -------------------------------
    if (tid == 0) {
        unsigned sup[7] = {0, 0, 0, 0, 0, 0, 0};
        #pragma unroll
        for (int w = 0; w < 7; w++) {
            unsigned kwv = 0;
            unsigned rowm = hasroww[w];
            unsigned pend = validw[w] & ~sup[w];
            while (pend) {
                unsigned r = pend & rowm;
                if (!r) { kwv |= pend; break; }
                int bsh = __ffs(r) - 1;
                unsigned below = (1u << bsh) - 1u;
                kwv |= pend & below;
                kwv |= 1u << bsh;
                int j = w * 32 + bsh;
                uint4 r1 = *(const uint4*)&rows[j * 8];
                uint4 r2 = *(const uint4*)&rows[j * 8 + 4];
                sup[0] |= r1.x; sup[1] |= r1.y; sup[2] |= r1.z; sup[3] |= r1.w;
                sup[4] |= r2.x; sup[5] |= r2.y; sup[6] |= r2.z;
                unsigned above = ~((below << 1) | 1u);
                pend = validw[w] & ~sup[w] & above;
            }
            keepw[w] = kwv;
        }
    }
    __syncthreads();

    // ---------------- compact & write ---------------------------------------
    if (tid < TOPK) {
        int w = tid >> 5, bs = tid & 31;
        unsigned kwv = keepw[w];
        if ((kwv >> bs) & 1u) {
            int pos = 0;
            #pragma unroll
            for (int ww = 0; ww < 7; ww++) if (ww < w) pos += __popc(keepw[ww]);
            pos += __popc(kwv & ((1u << bs) - 1u));
            float4 bx = boxs[tid];
            float* row = outBase + pos * 5;
            row[0] = scores[tid];
            row[1] = bx.x;
            row[2] = bx.y;
            row[3] = bx.z;
            row[4] = bx.w;
        }
    }
}

// ---------------------------------------------------------------------------
extern "C" void kernel_launch(void* const* d_in, const int* in_sizes, int n_in,
                              void* d_out, int out_size) {
    const float* loc   = (const float*)d_in[0];
    const float* conf  = (const float*)d_in[1];
    const float* prior = (const float*)d_in[2];
    float* out = (float*)d_out;

    void* histPtr = nullptr;
    cudaGetSymbolAddress(&histPtr, g_hist);
    cudaMemsetAsync(histPtr, 0, (size_t)NB * NC * NBIN * sizeof(unsigned), 0);

    const int nt = (NP + TP - 1) / TP;          // 18
    transpose_kernel<<<NB * nt, 256>>>(conf);
    pivot_kernel<<<NB * NC, 256>>>();
    select_kernel<<<NB * NC, NT>>>(loc, prior, out);
}